// round 1
// baseline (speedup 1.0000x reference)
#include <cuda_runtime.h>
#include <math.h>

#define N_IMG   512
#define N_ANG   25
#define N_DET   512
#define N_SAMP  1024
#define N_RAYS  (N_ANG * N_DET)

#define SRC_DIST 512.0f
#define DET_DIST 512.0f
#define DET_SPACING 3.0f

// p + u*v constrained to [lo, hi]; shrink [u0,u1]
__device__ __forceinline__ void clip_axis(float p, float v, float lo, float hi,
                                          float& u0, float& u1) {
    if (fabsf(v) < 1e-12f) {
        if (p < lo || p > hi) { u0 = 1e30f; u1 = -1e30f; }
    } else {
        float inv = 1.0f / v;
        float a = (lo - p) * inv;
        float b = (hi - p) * inv;
        float mn = fminf(a, b), mx = fmaxf(a, b);
        u0 = fmaxf(u0, mn);
        u1 = fminf(u1, mx);
    }
}

__device__ __forceinline__ float fetch(const float* __restrict__ img, int r, int c) {
    bool ok = (r >= 0) & (r < N_IMG) & (c >= 0) & (c < N_IMG);
    int rr = min(max(r, 0), N_IMG - 1);
    int cc = min(max(c, 0), N_IMG - 1);
    float v = __ldg(img + rr * N_IMG + cc);
    return ok ? v : 0.0f;
}

__global__ __launch_bounds__(256)
void fanbeam_kernel(const float* __restrict__ img, float* __restrict__ out) {
    int gwarp = (blockIdx.x * blockDim.x + threadIdx.x) >> 5;
    int lane  = threadIdx.x & 31;
    if (gwarp >= N_RAYS) return;

    int a = gwarp / N_DET;
    int d = gwarp - a * N_DET;

    // angle + geometry (all lanes redundantly; cheap per-ray)
    float beta = (float)a * (2.0f * 3.14159265358979323846f / (float)N_ANG);
    float s, c;
    sincosf(beta, &s, &c);

    float t  = ((float)d - (float)(N_DET - 1) * 0.5f) * DET_SPACING;
    float sx = -SRC_DIST * s;
    float sy =  SRC_DIST * c;
    float ex = t * c + DET_DIST * s;
    float ey = t * s - DET_DIST * c;
    float dx = ex - sx;
    float dy = ey - sy;
    float seg = sqrtf(dx * dx + dy * dy);

    const float half = (float)(N_IMG - 1) * 0.5f;   // 255.5
    float cA = sx + half;         // col(u) = cA + u*dx
    float rA = half - sy;         // row(u) = rA - u*dy

    // clip u in [0,1] to the slab where any bilinear texel can be nonzero:
    // row,col in (-1, N_IMG); use small margin so float rounding never drops
    // a genuinely nonzero sample (extra samples evaluate to 0 via masking).
    const float eps = 1e-3f;
    float u0 = 0.0f, u1 = 1.0f;
    clip_axis(cA,  dx, -1.0f - eps, (float)N_IMG + eps, u0, u1);
    clip_axis(rA, -dy, -1.0f - eps, (float)N_IMG + eps, u0, u1);

    float acc = 0.0f;
    const float inv_s = 1.0f / (float)N_SAMP;

    if (u0 <= u1) {
        int s0 = max(0, (int)floorf(u0 * (float)N_SAMP - 0.5f));
        int s1 = min(N_SAMP - 1, (int)ceilf(u1 * (float)N_SAMP - 0.5f));

        for (int i = s0 + lane; i <= s1; i += 32) {
            float u   = ((float)i + 0.5f) * inv_s;
            float col = fmaf(u, dx, cA);
            float row = fmaf(u, -dy, rA);

            float r0f = floorf(row);
            float c0f = floorf(col);
            float fr = row - r0f;
            float fc = col - c0f;
            int r0 = (int)r0f;
            int c0 = (int)c0f;

            float v00 = fetch(img, r0,     c0);
            float v01 = fetch(img, r0,     c0 + 1);
            float v10 = fetch(img, r0 + 1, c0);
            float v11 = fetch(img, r0 + 1, c0 + 1);

            float top = fmaf(fc, v01 - v00, v00);
            float bot = fmaf(fc, v11 - v10, v10);
            acc      += fmaf(fr, bot - top, top);
        }
    }

    // warp reduction
    #pragma unroll
    for (int o = 16; o > 0; o >>= 1)
        acc += __shfl_down_sync(0xffffffffu, acc, o);

    if (lane == 0)
        out[gwarp] = acc * seg * inv_s;
}

extern "C" void kernel_launch(void* const* d_in, const int* in_sizes, int n_in,
                              void* d_out, int out_size) {
    (void)in_sizes; (void)n_in; (void)out_size;
    const float* img = (const float*)d_in[0];
    float* out = (float*)d_out;
    // 12800 rays, 1 warp each, 8 warps/block -> 1600 blocks
    fanbeam_kernel<<<N_RAYS / 8, 256>>>(img, out);
}